// round 11
// baseline (speedup 1.0000x reference)
#include <cuda_runtime.h>
#include <cstdint>

// LayerNorm backward fused: golden_x [B,S,H], golden_gamma [H], golden_beta [H]
// B=4, S=4096, H=2048, fp32. Output layout: [x | gamma | beta] concatenated.
// R10: pair-processing — two rows per __syncthreads (6 partial sums, one
//      barrier), dsum staged via per-thread cp.async into smem (no register
//      cost), distance-2 register prefetch of dy/x1/x2 kept from R5.

#define HF 2048
#define ROWS 16384           // B*S
#define THREADS 256
#define GRID 296             // 148 SMs * 2 CTAs/SM -> single wave

__device__ __forceinline__ void cp16(uint32_t dst, const void* src) {
    asm volatile("cp.async.cg.shared.global [%0], [%1], 16;" :: "r"(dst), "l"(src));
}

__global__ __launch_bounds__(THREADS, 2) void ln_bwd_kernel(
    const float* __restrict__ dy,
    const float* __restrict__ x1,
    const float* __restrict__ x2,
    const float* __restrict__ rstd,
    const float* __restrict__ mean,
    const float* __restrict__ gamma,
    const float* __restrict__ dsum,
    float* __restrict__ out)
{
    __shared__ float red[2][6][8];
    __shared__ __align__(16) float dsbuf[2][HF];   // staged dsum rows A,B

    const int tid  = threadIdx.x;
    const int lane = tid & 31;
    const int wid  = tid >> 5;
    const int bid  = blockIdx.x;

    const int c0 = 4 * tid;          // 0..1020
    const int c1 = c0 + HF / 2;      // 1024..2044

    const uint32_t ds_s = (uint32_t)__cvta_generic_to_shared(dsbuf);

    const float4 g0 = *(const float4*)(gamma + c0);
    const float4 g1 = *(const float4*)(gamma + c1);
    float gv[8] = {g0.x, g0.y, g0.z, g0.w, g1.x, g1.y, g1.z, g1.w};

    float ag[8] = {0.f, 0.f, 0.f, 0.f, 0.f, 0.f, 0.f, 0.f};
    float ab[8] = {0.f, 0.f, 0.f, 0.f, 0.f, 0.f, 0.f, 0.f};

    const float inv_d = 1.0f / (float)HF;

    // ---- two register buffer sets: dy, x1, x2 (+ mean/rstd scalars) ----
    float4 Ady0, Ady1, Aa0, Aa1, Ab0, Ab1; float Amu = 0.f, Ars = 0.f;
    float4 Bdy0, Bdy1, Ba0, Ba1, Bb0, Bb1; float Bmu = 0.f, Brs = 0.f;

    #define LOADBUF(P, row)                                                  \
        if ((row) < ROWS) {                                                  \
            const size_t _b = (size_t)(row) * HF;                            \
            P##dy0 = __ldcs((const float4*)(dy + _b + c0));                  \
            P##dy1 = __ldcs((const float4*)(dy + _b + c1));                  \
            P##a0  = __ldcs((const float4*)(x1 + _b + c0));                  \
            P##a1  = __ldcs((const float4*)(x1 + _b + c1));                  \
            P##b0  = __ldcs((const float4*)(x2 + _b + c0));                  \
            P##b1  = __ldcs((const float4*)(x2 + _b + c1));                  \
            P##mu  = __ldcs(mean + (row));                                   \
            P##rs  = __ldcs(rstd + (row));                                   \
        }

    // consume buffer P into working arrays DYV/XH (frees P for refill)
    #define CONSUME(P, DYV, XH, RS)                                          \
        float DYV[8] = {P##dy0.x, P##dy0.y, P##dy0.z, P##dy0.w,              \
                        P##dy1.x, P##dy1.y, P##dy1.z, P##dy1.w};             \
        const float RS = P##rs;                                              \
        float XH[8];                                                         \
        {                                                                    \
            const float _mu = P##mu;                                         \
            XH[0] = P##a0.x + P##b0.x - _mu; XH[1] = P##a0.y + P##b0.y - _mu;\
            XH[2] = P##a0.z + P##b0.z - _mu; XH[3] = P##a0.w + P##b0.w - _mu;\
            XH[4] = P##a1.x + P##b1.x - _mu; XH[5] = P##a1.y + P##b1.y - _mu;\
            XH[6] = P##a1.z + P##b1.z - _mu; XH[7] = P##a1.w + P##b1.w - _mu;\
        }

    #define PARTSUM(DYV, XH, S1, S2, S3)                                     \
        float S1 = 0.f, S2 = 0.f, S3 = 0.f;                                  \
        _Pragma("unroll")                                                    \
        for (int k = 0; k < 8; k++) {                                        \
            const float pdxl = DYV[k] * gv[k];                               \
            S1 = fmaf(pdxl, XH[k], S1);                                      \
            S2 += pdxl;                                                      \
            S3 += XH[k];                                                     \
        }

    #define EPILOGUE(DYV, XH, RS, T1, T2, T3, DS0, DS1, BASE)                \
    {                                                                        \
        const float rs3     = (RS) * (RS) * (RS);                            \
        const float pd_var  = -0.5f * (T1) * rs3;                            \
        const float pd_mean = -(T2) * (RS) + pd_var * (-2.0f * inv_d) * (T3);\
        const float coef    = pd_var * (2.0f * inv_d);                       \
        const float cmean   = pd_mean * inv_d;                               \
        float ov[8];                                                         \
        _Pragma("unroll")                                                    \
        for (int k = 0; k < 8; k++) {                                        \
            const float pdxl = DYV[k] * gv[k];                               \
            ov[k] = fmaf(pdxl, RS, fmaf(coef, XH[k], cmean));                \
            ag[k] = fmaf(DYV[k] * XH[k], RS, ag[k]);                         \
            ab[k] += DYV[k];                                                 \
        }                                                                    \
        ov[0] += DS0.x; ov[1] += DS0.y; ov[2] += DS0.z; ov[3] += DS0.w;      \
        ov[4] += DS1.x; ov[5] += DS1.y; ov[6] += DS1.z; ov[7] += DS1.w;      \
        __stcs((float4*)(out + (BASE) + c0),                                 \
               make_float4(ov[0], ov[1], ov[2], ov[3]));                     \
        __stcs((float4*)(out + (BASE) + c1),                                 \
               make_float4(ov[4], ov[5], ov[6], ov[7]));                     \
    }

    // ---- prologue ----
    LOADBUF(A, bid);
    LOADBUF(B, bid + GRID);

    int r = bid;
    int par = 0;
    while (r + GRID < ROWS) {
        const size_t baseA = (size_t)r * HF;
        const size_t baseB = baseA + (size_t)GRID * HF;

        // consume A, refill A (distance-2)
        CONSUME(A, dyvA, xhA, rsA);
        LOADBUF(A, r + 2 * GRID);
        // consume B, refill B
        CONSUME(B, dyvB, xhB, rsB);
        LOADBUF(B, r + 3 * GRID);

        // stage both rows' dsum chunks this thread will read (per-thread copy,
        // no cross-thread dependency -> wait_group is sufficient, no barrier)
        cp16(ds_s + c0 * 4,          dsum + baseA + c0);
        cp16(ds_s + c1 * 4,          dsum + baseA + c1);
        cp16(ds_s + HF * 4 + c0 * 4, dsum + baseB + c0);
        cp16(ds_s + HF * 4 + c1 * 4, dsum + baseB + c1);
        asm volatile("cp.async.commit_group;" ::: "memory");

        // 6 partial sums, 6 warp-reduce chains
        PARTSUM(dyvA, xhA, sA1, sA2, sA3);
        PARTSUM(dyvB, xhB, sB1, sB2, sB3);
        #pragma unroll
        for (int off = 16; off > 0; off >>= 1) {
            sA1 += __shfl_xor_sync(0xFFFFFFFFu, sA1, off);
            sA2 += __shfl_xor_sync(0xFFFFFFFFu, sA2, off);
            sA3 += __shfl_xor_sync(0xFFFFFFFFu, sA3, off);
            sB1 += __shfl_xor_sync(0xFFFFFFFFu, sB1, off);
            sB2 += __shfl_xor_sync(0xFFFFFFFFu, sB2, off);
            sB3 += __shfl_xor_sync(0xFFFFFFFFu, sB3, off);
        }
        if (lane == 0) {
            red[par][0][wid] = sA1; red[par][1][wid] = sA2;
            red[par][2][wid] = sA3; red[par][3][wid] = sB1;
            red[par][4][wid] = sB2; red[par][5][wid] = sB3;
        }
        __syncthreads();                       // ONE barrier for two rows
        float tA1 = 0.f, tA2 = 0.f, tA3 = 0.f;
        float tB1 = 0.f, tB2 = 0.f, tB3 = 0.f;
        #pragma unroll
        for (int w = 0; w < 8; w++) {
            tA1 += red[par][0][w]; tA2 += red[par][1][w];
            tA3 += red[par][2][w]; tB1 += red[par][3][w];
            tB2 += red[par][4][w]; tB3 += red[par][5][w];
        }

        asm volatile("cp.async.wait_group 0;" ::: "memory");
        {
            const float4 dA0 = *(const float4*)(&dsbuf[0][c0]);
            const float4 dA1 = *(const float4*)(&dsbuf[0][c1]);
            EPILOGUE(dyvA, xhA, rsA, tA1, tA2, tA3, dA0, dA1, baseA);
        }
        {
            const float4 dB0 = *(const float4*)(&dsbuf[1][c0]);
            const float4 dB1 = *(const float4*)(&dsbuf[1][c1]);
            EPILOGUE(dyvB, xhB, rsB, tB1, tB2, tB3, dB0, dB1, baseB);
        }

        r += 2 * GRID;
        par ^= 1;
    }

    // ---- tail: lone last row (CTAs with an odd row count), uses buffer A ----
    if (r < ROWS) {
        const size_t base = (size_t)r * HF;
        CONSUME(A, dyvT, xhT, rsT);
        const float4 dT0 = __ldcs((const float4*)(dsum + base + c0));
        const float4 dT1 = __ldcs((const float4*)(dsum + base + c1));
        PARTSUM(dyvT, xhT, sT1, sT2, sT3);
        #pragma unroll
        for (int off = 16; off > 0; off >>= 1) {
            sT1 += __shfl_xor_sync(0xFFFFFFFFu, sT1, off);
            sT2 += __shfl_xor_sync(0xFFFFFFFFu, sT2, off);
            sT3 += __shfl_xor_sync(0xFFFFFFFFu, sT3, off);
        }
        if (lane == 0) {
            red[par][0][wid] = sT1; red[par][1][wid] = sT2;
            red[par][2][wid] = sT3;
        }
        __syncthreads();
        float t1 = 0.f, t2 = 0.f, t3 = 0.f;
        #pragma unroll
        for (int w = 0; w < 8; w++) {
            t1 += red[par][0][w]; t2 += red[par][1][w]; t3 += red[par][2][w];
        }
        EPILOGUE(dyvT, xhT, rsT, t1, t2, t3, dT0, dT1, base);
    }

    // flush dgamma/dbeta partials: 296 CTAs * 4096 atomics -> negligible
    float* gout = out + (size_t)ROWS * HF;
    float* bout = gout + HF;
    #pragma unroll
    for (int k = 0; k < 4; k++) {
        atomicAdd(gout + c0 + k, ag[k]);
        atomicAdd(gout + c1 + k, ag[4 + k]);
        atomicAdd(bout + c0 + k, ab[k]);
        atomicAdd(bout + c1 + k, ab[4 + k]);
    }
}

extern "C" void kernel_launch(void* const* d_in, const int* in_sizes, int n_in,
                              void* d_out, int out_size) {
    const float* dy    = (const float*)d_in[0];
    const float* x1    = (const float*)d_in[1];
    const float* x2    = (const float*)d_in[2];
    const float* rstd  = (const float*)d_in[3];
    const float* mean  = (const float*)d_in[4];
    const float* gamma = (const float*)d_in[5];
    const float* dsum  = (const float*)d_in[6];
    float* out = (float*)d_out;

    // zero the dgamma/dbeta region via a memset node (cheap, capturable)
    cudaMemsetAsync(out + (size_t)ROWS * HF, 0, 2 * HF * sizeof(float));

    ln_bwd_kernel<<<GRID, THREADS>>>(dy, x1, x2, rstd, mean, gamma, dsum, out);
}